// round 2
// baseline (speedup 1.0000x reference)
#include <cuda_runtime.h>
#include <cuda_fp16.h>
#include <cstdint>

// ---------------------------------------------------------------------------
// Fully fused persistent LSTM classifier.
// Grid: 128 CTAs x 256 threads, B_tile = 8 batch rows per CTA (single wave).
// Per time step (merged): gates_L1(t) and gates_L0(t+1) via mma.sync f16,
// then both LSTM cells elementwise. c-state fp32 in registers, h via smem fp16.
// Weights staged once in smem (fp16, padded rows -> conflict-free LDS).
// x prefetched 2 steps ahead (LDG.128 -> regs -> STS next cell phase).
// Head (proj/fc1/fc2) computed per-CTA from smem h_final, fp32.
// ---------------------------------------------------------------------------

namespace {

constexpr int T_ = 512, I_ = 128, H_ = 64, G4 = 256, E_ = 128, C_ = 100;
constexpr int BT = 8;
constexpr int NCTA = 128, NTHR = 256;

// smem strides (in elements)
constexpr int SWI0 = 136;   // W_ih0 row stride (halves), K=128 + 8 pad
constexpr int SWH  = 72;    // K=64 weight row stride (halves)
constexpr int SXS  = 136;   // x tile row stride (halves)
constexpr int SHS  = 72;    // h tile row stride (halves)
constexpr int SGS  = 264;   // gate buffer row stride (floats)

// smem byte offsets (all 16B aligned)
constexpr int OFF_WIH0 = 0;                      // 256*136*2 = 69632
constexpr int OFF_WHH0 = 69632;                  // 256*72*2  = 36864
constexpr int OFF_WIH1 = 106496;
constexpr int OFF_WHH1 = 143360;
constexpr int OFF_B0   = 180224;                 // 256 f32
constexpr int OFF_B1   = 181248;
constexpr int OFF_X    = 182272;                 // 8*136*2 = 2176
constexpr int OFF_H0   = 184448;                 // 8*72*2  = 1152
constexpr int OFF_H1   = 185600;
constexpr int OFF_G0   = 186752;                 // 8*264*4 = 8448
constexpr int OFF_G1   = 195200;
constexpr int OFF_HF   = 203648;                 // 8*64*4  = 2048 (h1 final, fp32)
constexpr int OFF_E    = 205696;                 // 8*128*4 = 4096
constexpr int OFF_F    = 209792;                 // 4096
constexpr int SMEM_TOTAL = 213888;

__device__ __forceinline__ float fast_sigmoid(float v) {
    return __fdividef(1.f, 1.f + __expf(-v));
}
__device__ __forceinline__ float fast_tanh(float v) {
    return 2.f * __fdividef(1.f, 1.f + __expf(-2.f * v)) - 1.f;
}

__device__ __forceinline__ void mma16816(float c[4], uint32_t a0, uint32_t a2,
                                         uint32_t b0, uint32_t b1) {
    asm volatile(
        "mma.sync.aligned.m16n8k16.row.col.f32.f16.f16.f32 "
        "{%0,%1,%2,%3},{%4,%5,%6,%7},{%8,%9},{%0,%1,%2,%3};\n"
        : "+f"(c[0]), "+f"(c[1]), "+f"(c[2]), "+f"(c[3])
        : "r"(a0), "r"(0u), "r"(a2), "r"(0u), "r"(b0), "r"(b1));
}

// C[16 x 32w..] += A[8 x 16*KT] * W[256 x 16*KT]^T ; rows 8..15 of A are zero
// (a1 = a3 = 0), warp handles gate columns [nb, nb+32).
template <int KT, int SA, int SW>
__device__ __forceinline__ void gemm_acc(const half* __restrict__ A,
                                         const half* __restrict__ W,
                                         int nb, int gq, int tt, float acc[4][4]) {
#pragma unroll
    for (int kt = 0; kt < KT; kt++) {
        const int kb = kt * 16;
        uint32_t a0 = *(const uint32_t*)(A + gq * SA + kb + 2 * tt);
        uint32_t a2 = *(const uint32_t*)(A + gq * SA + kb + 8 + 2 * tt);
#pragma unroll
        for (int nt = 0; nt < 4; nt++) {
            const half* wp = W + (nb + nt * 8 + gq) * SW + kb + 2 * tt;
            uint32_t b0 = *(const uint32_t*)(wp);
            uint32_t b1 = *(const uint32_t*)(wp + 8);
            mma16816(acc[nt], a0, a2, b0, b1);
        }
    }
}

__device__ __forceinline__ void init_acc(float acc[4][4], const float* __restrict__ sB,
                                         int nb, int tt) {
#pragma unroll
    for (int nt = 0; nt < 4; nt++) {
        float v0 = sB[nb + nt * 8 + 2 * tt];
        float v1 = sB[nb + nt * 8 + 2 * tt + 1];
        acc[nt][0] = v0; acc[nt][1] = v1;
        acc[nt][2] = v0; acc[nt][3] = v1;   // rows 8..15: unused
    }
}

__device__ __forceinline__ void store_gates(float* __restrict__ sG, const float acc[4][4],
                                            int nb, int gq, int tt) {
#pragma unroll
    for (int nt = 0; nt < 4; nt++) {
        *(float2*)(sG + gq * SGS + nb + nt * 8 + 2 * tt) =
            make_float2(acc[nt][0], acc[nt][1]);
    }
}

__global__ void __launch_bounds__(NTHR, 1)
lstm_fused(const float* __restrict__ x,
           const float* __restrict__ Wih0, const float* __restrict__ Whh0,
           const float* __restrict__ bih0, const float* __restrict__ bhh0,
           const float* __restrict__ Wih1, const float* __restrict__ Whh1,
           const float* __restrict__ bih1, const float* __restrict__ bhh1,
           const float* __restrict__ Wproj, const float* __restrict__ bproj,
           const float* __restrict__ Wfc1, const float* __restrict__ bfc1,
           const float* __restrict__ Wfc2, const float* __restrict__ bfc2,
           float* __restrict__ out)
{
    extern __shared__ unsigned char smem[];
    half*  sWih0 = (half*)(smem + OFF_WIH0);
    half*  sWhh0 = (half*)(smem + OFF_WHH0);
    half*  sWih1 = (half*)(smem + OFF_WIH1);
    half*  sWhh1 = (half*)(smem + OFF_WHH1);
    float* sB0   = (float*)(smem + OFF_B0);
    float* sB1   = (float*)(smem + OFF_B1);
    half*  sX    = (half*)(smem + OFF_X);
    half*  sH0   = (half*)(smem + OFF_H0);
    half*  sH1   = (half*)(smem + OFF_H1);
    float* sG0   = (float*)(smem + OFF_G0);
    float* sG1   = (float*)(smem + OFF_G1);
    float* sHF   = (float*)(smem + OFF_HF);
    float* sE    = (float*)(smem + OFF_E);
    float* sF    = (float*)(smem + OFF_F);

    const int tid  = threadIdx.x;
    const int lane = tid & 31;
    const int wid  = tid >> 5;
    const int gq   = lane >> 2;     // mma "groupID"
    const int tt   = lane & 3;      // mma "threadID in group"
    const int nb   = wid * 32;      // this warp's gate base
    const int b0   = blockIdx.x * BT;

    // ---- stage weights (fp16) + fused biases into smem ----
    for (int i = tid; i < G4 * I_; i += NTHR)
        sWih0[(i >> 7) * SWI0 + (i & 127)] = __float2half(Wih0[i]);
    for (int i = tid; i < G4 * H_; i += NTHR) {
        int g = i >> 6, k = i & 63;
        sWhh0[g * SWH + k] = __float2half(Whh0[i]);
        sWih1[g * SWH + k] = __float2half(Wih1[i]);
        sWhh1[g * SWH + k] = __float2half(Whh1[i]);
    }
    for (int i = tid; i < G4; i += NTHR) {
        sB0[i] = bih0[i] + bhh0[i];
        sB1[i] = bih1[i] + bhh1[i];
    }
    for (int i = tid; i < BT * SHS; i += NTHR) {
        sH0[i] = __float2half(0.f);
        sH1[i] = __float2half(0.f);
    }

    // ---- x prefetch pipeline: one LDG.128 per thread per step ----
    const int xr = tid >> 5;          // batch row 0..7 (one warp per row)
    const int xi = lane * 4;          // 4 contiguous floats
    const float* xrow = x + ((size_t)(b0 + xr) * T_) * I_ + xi;

    float4 xv = *(const float4*)(xrow);          // t = 0
    {
        *(half2*)(sX + xr * SXS + xi)     = __floats2half2_rn(xv.x, xv.y);
        *(half2*)(sX + xr * SXS + xi + 2) = __floats2half2_rn(xv.z, xv.w);
    }
    float4 xpre = *(const float4*)(xrow + I_);   // t = 1
    __syncthreads();

    float cst0[2] = {0.f, 0.f}, cst1[2] = {0.f, 0.f};

    // ---- prologue: layer0 gates for t=0 (h0(-1) = 0 -> no recurrent term) ----
    {
        float acc[4][4];
        init_acc(acc, sB0, nb, tt);
        gemm_acc<8, SXS, SWI0>(sX, sWih0, nb, gq, tt, acc);
        store_gates(sG0, acc, nb, gq, tt);
    }
    __syncthreads();
    {
#pragma unroll
        for (int q = 0; q < 2; q++) {
            int item = tid + q * NTHR;
            int r = item >> 6, j = item & 63;
            const float* g = sG0 + r * SGS;
            float iv = fast_sigmoid(g[j]);
            float fv = fast_sigmoid(g[64 + j]);
            float gv = fast_tanh(g[128 + j]);
            float ov = fast_sigmoid(g[192 + j]);
            float c  = fv * cst0[q] + iv * gv;
            cst0[q]  = c;
            sH0[r * SHS + j] = __float2half(ov * fast_tanh(c));
        }
        *(half2*)(sX + xr * SXS + xi)     = __floats2half2_rn(xpre.x, xpre.y);
        *(half2*)(sX + xr * SXS + xi + 2) = __floats2half2_rn(xpre.z, xpre.w);
        xpre = *(const float4*)(xrow + 2 * (size_t)I_);     // t = 2
    }
    __syncthreads();

    // ---- main loop: iteration k computes L1 cell(t=k) and L0 cell(t=k+1) ----
    // invariant at loop top: sH0 = h0(k), sH1 = h1(k-1), sX = x(k+1), xpre = x(k+2)
    for (int k = 0; k < T_; k++) {
        float accL1[4][4], accL0[4][4];
        init_acc(accL1, sB1, nb, tt);
        init_acc(accL0, sB0, nb, tt);
        gemm_acc<4, SHS, SWH >(sH0, sWih1, nb, gq, tt, accL1);
        gemm_acc<4, SHS, SWH >(sH1, sWhh1, nb, gq, tt, accL1);
        gemm_acc<8, SXS, SWI0>(sX,  sWih0, nb, gq, tt, accL0);
        gemm_acc<4, SHS, SWH >(sH0, sWhh0, nb, gq, tt, accL0);
        store_gates(sG1, accL1, nb, gq, tt);
        store_gates(sG0, accL0, nb, gq, tt);
        __syncthreads();

        const bool last = (k == T_ - 1);
#pragma unroll
        for (int q = 0; q < 2; q++) {
            int item = tid + q * NTHR;
            int r = item >> 6, j = item & 63;
            {   // layer 1 cell (t = k)
                const float* g = sG1 + r * SGS;
                float iv = fast_sigmoid(g[j]);
                float fv = fast_sigmoid(g[64 + j]);
                float gv = fast_tanh(g[128 + j]);
                float ov = fast_sigmoid(g[192 + j]);
                float c  = fv * cst1[q] + iv * gv;
                cst1[q]  = c;
                float h  = ov * fast_tanh(c);
                sH1[r * SHS + j] = __float2half(h);
                if (last) sHF[r * H_ + j] = h;
            }
            {   // layer 0 cell (t = k+1; harmless phantom at k = T_-1)
                const float* g = sG0 + r * SGS;
                float iv = fast_sigmoid(g[j]);
                float fv = fast_sigmoid(g[64 + j]);
                float gv = fast_tanh(g[128 + j]);
                float ov = fast_sigmoid(g[192 + j]);
                float c  = fv * cst0[q] + iv * gv;
                cst0[q]  = c;
                sH0[r * SHS + j] = __float2half(ov * fast_tanh(c));
            }
        }
        {   // x pipeline: commit x(k+2), fetch x(k+3)
            *(half2*)(sX + xr * SXS + xi)     = __floats2half2_rn(xpre.x, xpre.y);
            *(half2*)(sX + xr * SXS + xi + 2) = __floats2half2_rn(xpre.z, xpre.w);
            int tn = k + 3; if (tn > T_ - 1) tn = T_ - 1;
            xpre = *(const float4*)(xrow + (size_t)tn * I_);
        }
        __syncthreads();
    }

    // ---- head: emb = relu(h1 Wp^T + bp); hid = relu(emb W1^T + b1); logits ----
#pragma unroll
    for (int q = 0; q < 4; q++) {
        int idx = tid + q * NTHR;                 // 8*128 outputs
        int r = idx >> 7, e = idx & 127;
        float a = bproj[e];
        const float* wp = Wproj + e * H_;
        const float* hp = sHF + r * H_;
#pragma unroll 8
        for (int kk = 0; kk < H_; kk++) a += hp[kk] * wp[kk];
        sE[r * E_ + e] = fmaxf(a, 0.f);
    }
    __syncthreads();
#pragma unroll
    for (int q = 0; q < 4; q++) {
        int idx = tid + q * NTHR;
        int r = idx >> 7, e = idx & 127;
        float a = bfc1[e];
        const float* wp = Wfc1 + e * E_;
        const float* hp = sE + r * E_;
#pragma unroll 8
        for (int kk = 0; kk < E_; kk++) a += hp[kk] * wp[kk];
        sF[r * E_ + e] = fmaxf(a, 0.f);
    }
    __syncthreads();
    for (int idx = tid; idx < BT * C_; idx += NTHR) {
        int r = idx / C_, c = idx - r * C_;
        float a = bfc2[c];
        const float* wp = Wfc2 + c * E_;
        const float* hp = sF + r * E_;
#pragma unroll 8
        for (int kk = 0; kk < E_; kk++) a += hp[kk] * wp[kk];
        out[(size_t)(b0 + r) * C_ + c] = a;
    }
}

}  // namespace

extern "C" void kernel_launch(void* const* d_in, const int* in_sizes, int n_in,
                              void* d_out, int out_size) {
    cudaFuncSetAttribute(lstm_fused, cudaFuncAttributeMaxDynamicSharedMemorySize,
                         SMEM_TOTAL);
    lstm_fused<<<NCTA, NTHR, SMEM_TOTAL>>>(
        (const float*)d_in[0],
        (const float*)d_in[1],  (const float*)d_in[2],
        (const float*)d_in[3],  (const float*)d_in[4],
        (const float*)d_in[5],  (const float*)d_in[6],
        (const float*)d_in[7],  (const float*)d_in[8],
        (const float*)d_in[9],  (const float*)d_in[10],
        (const float*)d_in[11], (const float*)d_in[12],
        (const float*)d_in[13], (const float*)d_in[14],
        (float*)d_out);
}

// round 3
// speedup vs baseline: 1.7939x; 1.7939x over previous
#include <cuda_runtime.h>
#include <cuda_fp16.h>
#include <cstdint>

// ---------------------------------------------------------------------------
// Fused persistent LSTM classifier, v2.
// GEMM role swap: W = A operand (M=16 gate rows, permuted so each warp's two
// M-tiles are {i|f} and {g|o} of the same 8 hidden units), activations = B
// operand (N=8 batch). Weight fragments + biases resident in registers for all
// 512 steps. Gates never touch smem: each thread's accumulators hold i,f,g,o
// for its (2 batch x 1 hidden) cells; c-state in registers. h/x double-
// buffered in smem -> ONE __syncthreads per time step.
// ---------------------------------------------------------------------------

namespace {

constexpr int T_ = 512, I_ = 128, H_ = 64, E_ = 128, C_ = 100;
constexpr int BT = 8, NCTA = 128, NTHR = 256;

// smem strides (elements)
constexpr int SWI = 136;   // W_ih0 rows (K=128 halves + pad)
constexpr int SWH = 72;    // K=64 weight rows
constexpr int SXS = 136;   // x tile rows (conflict-free: (g*68+t)%32 all distinct)
constexpr int SHS = 72;    // h tile rows (conflict-free: (g*36+t)%32 all distinct)

// smem offsets (bytes, 16B aligned)
constexpr int OFF_WIH0 = 0;        // 256*136*2 = 69632
constexpr int OFF_WHH0 = 69632;    // 256*72*2  = 36864
constexpr int OFF_WIH1 = 106496;
constexpr int OFF_WHH1 = 143360;
constexpr int OFF_B0   = 180224;   // 256 f32
constexpr int OFF_B1   = 181248;
constexpr int OFF_X    = 182272;   // 2 bufs * 8*136*2 = 4352
constexpr int OFF_H0   = 186624;   // 2 bufs * 8*72*2  = 2304
constexpr int OFF_H1   = 188928;
constexpr int OFF_HF   = 191232;   // 8*64 f32
constexpr int OFF_E    = 193280;   // 8*128 f32
constexpr int OFF_F    = 197376;
constexpr int SMEM_TOTAL = 201472;

__device__ __forceinline__ float fsig(float v) {
    return __fdividef(1.f, 1.f + __expf(-v));
}
__device__ __forceinline__ float ftanh(float v) {
    return 2.f * __fdividef(1.f, 1.f + __expf(-2.f * v)) - 1.f;
}

// D = A*B + D, m16n8k16 f16->f32. a[0..3] per PTX row.col layout.
__device__ __forceinline__ void mma4(float c[4], const uint32_t a[4],
                                     uint32_t b0, uint32_t b1) {
    asm volatile(
        "mma.sync.aligned.m16n8k16.row.col.f32.f16.f16.f32 "
        "{%0,%1,%2,%3},{%4,%5,%6,%7},{%8,%9},{%0,%1,%2,%3};\n"
        : "+f"(c[0]), "+f"(c[1]), "+f"(c[2]), "+f"(c[3])
        : "r"(a[0]), "r"(a[1]), "r"(a[2]), "r"(a[3]), "r"(b0), "r"(b1));
}

// One-time: pull this warp's A-fragments (W rows, permuted) into registers.
// a0=A[g][2t..], a1=A[g+8][..], a2=A[g][2t+8..], a3=A[g+8][2t+8..]
template <int KT, int S>
__device__ __forceinline__ void load_w(const half* __restrict__ sW, int w, int g,
                                       int t, uint32_t f[KT][2][4]) {
#pragma unroll
    for (int kt = 0; kt < KT; kt++)
#pragma unroll
        for (int u = 0; u < 2; u++) {
            const half* p = sW + (w * 32 + u * 16 + g) * S + kt * 16 + 2 * t;
            f[kt][u][0] = *(const uint32_t*)(p);
            f[kt][u][1] = *(const uint32_t*)(p + 8 * S);
            f[kt][u][2] = *(const uint32_t*)(p + 8);
            f[kt][u][3] = *(const uint32_t*)(p + 8 * S + 8);
        }
}

// Per-step: B-fragments from activations stored [batch(n)][k] row-major.
// b0 = act[n=g][2t,2t+1], b1 = act[g][2t+8,2t+9].
template <int KT, int S>
__device__ __forceinline__ void load_b(const half* __restrict__ A, int g, int t,
                                       uint32_t b[KT][2]) {
#pragma unroll
    for (int kt = 0; kt < KT; kt++) {
        const half* p = A + g * S + kt * 16 + 2 * t;
        b[kt][0] = *(const uint32_t*)(p);
        b[kt][1] = *(const uint32_t*)(p + 8);
    }
}

__device__ __forceinline__ void acc_init(float a[2][4], const float b[2][2]) {
#pragma unroll
    for (int u = 0; u < 2; u++) {
        a[u][0] = b[u][0]; a[u][1] = b[u][0];   // rows g   (v=0): n0, n1
        a[u][2] = b[u][1]; a[u][3] = b[u][1];   // rows g+8 (v=1)
    }
}

__global__ void __launch_bounds__(NTHR, 1)
lstm_fused(const float* __restrict__ x,
           const float* __restrict__ Wih0, const float* __restrict__ Whh0,
           const float* __restrict__ bih0, const float* __restrict__ bhh0,
           const float* __restrict__ Wih1, const float* __restrict__ Whh1,
           const float* __restrict__ bih1, const float* __restrict__ bhh1,
           const float* __restrict__ Wproj, const float* __restrict__ bproj,
           const float* __restrict__ Wfc1, const float* __restrict__ bfc1,
           const float* __restrict__ Wfc2, const float* __restrict__ bfc2,
           float* __restrict__ out)
{
    extern __shared__ unsigned char smem[];
    half*  sWih0 = (half*)(smem + OFF_WIH0);
    half*  sWhh0 = (half*)(smem + OFF_WHH0);
    half*  sWih1 = (half*)(smem + OFF_WIH1);
    half*  sWhh1 = (half*)(smem + OFF_WHH1);
    float* sB0   = (float*)(smem + OFF_B0);
    float* sB1   = (float*)(smem + OFF_B1);
    half*  sX    = (half*)(smem + OFF_X);
    half*  sH0   = (half*)(smem + OFF_H0);
    half*  sH1   = (half*)(smem + OFF_H1);
    float* sHF   = (float*)(smem + OFF_HF);
    float* sE    = (float*)(smem + OFF_E);
    float* sF    = (float*)(smem + OFF_F);

    const int tid  = threadIdx.x;
    const int lane = tid & 31;
    const int w    = tid >> 5;
    const int g    = lane >> 2;       // mma groupID
    const int t    = lane & 3;        // mma threadID-in-group
    const int b0r  = blockIdx.x * BT;

    // ---- stage weights permuted: perm row p -> orig gate row m ----
    // p = w*32 + u*16 + v*8 + r  <->  m = (2u+v)*64 + w*8 + r  (u,v,gate: i,f,g,o)
    for (int i = tid; i < 256 * 128; i += NTHR) {
        int p = i >> 7, k = i & 127;
        int m = (((p >> 4) & 1) * 2 + ((p >> 3) & 1)) * 64 + (p >> 5) * 8 + (p & 7);
        sWih0[p * SWI + k] = __float2half(Wih0[m * 128 + k]);
    }
    for (int i = tid; i < 256 * 64; i += NTHR) {
        int p = i >> 6, k = i & 63;
        int m = (((p >> 4) & 1) * 2 + ((p >> 3) & 1)) * 64 + (p >> 5) * 8 + (p & 7);
        sWhh0[p * SWH + k] = __float2half(Whh0[m * 64 + k]);
        sWih1[p * SWH + k] = __float2half(Wih1[m * 64 + k]);
        sWhh1[p * SWH + k] = __float2half(Whh1[m * 64 + k]);
    }
    for (int i = tid; i < 256; i += NTHR) {
        sB0[i] = bih0[i] + bhh0[i];
        sB1[i] = bih1[i] + bhh1[i];
    }
    for (int i = tid; i < 2 * BT * SHS; i += NTHR) {
        sH0[i] = __float2half(0.f);
        sH1[i] = __float2half(0.f);
    }

    // ---- x pipeline: warp = batch row, lane = 4 contiguous floats ----
    const int xr = w, xi = lane * 4;
    const float* xrow = x + ((size_t)(b0r + xr) * T_) * I_ + xi;
    {   // x(0) -> sX buf1 (prologue scratch)
        float4 xv = *(const float4*)(xrow);
        half* xw = sX + BT * SXS;
        *(half2*)(xw + xr * SXS + xi)     = __floats2half2_rn(xv.x, xv.y);
        *(half2*)(xw + xr * SXS + xi + 2) = __floats2half2_rn(xv.z, xv.w);
    }
    float4 xpre = *(const float4*)(xrow + I_);   // x(1)
    __syncthreads();

    // ---- weight frags + biases into registers (persist all 512 steps) ----
    uint32_t fih0[8][2][4], fhh0[4][2][4], fih1[4][2][4], fhh1[4][2][4];
    load_w<8, SWI>(sWih0, w, g, t, fih0);
    load_w<4, SWH>(sWhh0, w, g, t, fhh0);
    load_w<4, SWH>(sWih1, w, g, t, fih1);
    load_w<4, SWH>(sWhh1, w, g, t, fhh1);
    float bb0[2][2], bb1[2][2];
#pragma unroll
    for (int u = 0; u < 2; u++)
#pragma unroll
        for (int v = 0; v < 2; v++) {
            bb0[u][v] = sB0[(2 * u + v) * 64 + w * 8 + g];
            bb1[u][v] = sB1[(2 * u + v) * 64 + w * 8 + g];
        }

    const int n0 = 2 * t;          // this thread's two batch rows: n0, n0+1
    const int j  = w * 8 + g;      // this thread's hidden unit
    float c00 = 0.f, c01 = 0.f, c10 = 0.f, c11 = 0.f;

    // ---- prologue: L0 gates/cell for t=0 (h(-1)=0, recurrent term skipped) ----
    {
        uint32_t bx[8][2];
        load_b<8, SXS>(sX + BT * SXS, g, t, bx);
        float aL0[2][4];
        acc_init(aL0, bb0);
#pragma unroll
        for (int kt = 0; kt < 8; kt++)
#pragma unroll
            for (int u = 0; u < 2; u++)
                mma4(aL0[u], fih0[kt][u], bx[kt][0], bx[kt][1]);
        float i0 = fsig(aL0[0][0]), i1 = fsig(aL0[0][1]);
        float f0 = fsig(aL0[0][2]), f1 = fsig(aL0[0][3]);
        float g0 = ftanh(aL0[1][0]), g1 = ftanh(aL0[1][1]);
        float o0 = fsig(aL0[1][2]), o1 = fsig(aL0[1][3]);
        c00 = i0 * g0; c01 = i1 * g1;
        (void)f0; (void)f1;
        sH0[n0 * SHS + j]       = __float2half(o0 * ftanh(c00));
        sH0[(n0 + 1) * SHS + j] = __float2half(o1 * ftanh(c01));
        // x(1) -> sX buf0 ; fetch x(2)
        half* xw = sX;
        *(half2*)(xw + xr * SXS + xi)     = __floats2half2_rn(xpre.x, xpre.y);
        *(half2*)(xw + xr * SXS + xi + 2) = __floats2half2_rn(xpre.z, xpre.w);
        xpre = *(const float4*)(xrow + 2 * (size_t)I_);
    }
    __syncthreads();

    // ---- main loop: step k does L1 cell(t=k) and L0 cell(t=k+1) ----
    // reads buf p=k&1: sH0[p]=h0(k), sH1[p]=h1(k-1), sX[p]=x(k+1); writes buf 1-p
    for (int k = 0; k < T_; k++) {
        const int p = k & 1;
        uint32_t bx[8][2], bh0[4][2], bh1[4][2];
        load_b<8, SXS>(sX + p * (BT * SXS), g, t, bx);
        load_b<4, SHS>(sH0 + p * (BT * SHS), g, t, bh0);
        load_b<4, SHS>(sH1 + p * (BT * SHS), g, t, bh1);

        float aL1[2][4], aL0[2][4];
        acc_init(aL1, bb1);
        acc_init(aL0, bb0);
#pragma unroll
        for (int kt = 0; kt < 4; kt++)
#pragma unroll
            for (int u = 0; u < 2; u++) {
                mma4(aL1[u], fih1[kt][u], bh0[kt][0], bh0[kt][1]);
                mma4(aL1[u], fhh1[kt][u], bh1[kt][0], bh1[kt][1]);
                mma4(aL0[u], fhh0[kt][u], bh0[kt][0], bh0[kt][1]);
            }
#pragma unroll
        for (int kt = 0; kt < 8; kt++)
#pragma unroll
            for (int u = 0; u < 2; u++)
                mma4(aL0[u], fih0[kt][u], bx[kt][0], bx[kt][1]);

        half* h1w = sH1 + (1 - p) * (BT * SHS);
        half* h0w = sH0 + (1 - p) * (BT * SHS);

        {   // layer-1 cell, t = k  (gates already in this thread's regs)
            float i0 = fsig(aL1[0][0]), i1 = fsig(aL1[0][1]);
            float f0 = fsig(aL1[0][2]), f1 = fsig(aL1[0][3]);
            float g0 = ftanh(aL1[1][0]), g1 = ftanh(aL1[1][1]);
            float o0 = fsig(aL1[1][2]), o1 = fsig(aL1[1][3]);
            c10 = f0 * c10 + i0 * g0;
            c11 = f1 * c11 + i1 * g1;
            float h0v = o0 * ftanh(c10), h1v = o1 * ftanh(c11);
            h1w[n0 * SHS + j]       = __float2half(h0v);
            h1w[(n0 + 1) * SHS + j] = __float2half(h1v);
            if (k == T_ - 1) {
                sHF[n0 * H_ + j]       = h0v;
                sHF[(n0 + 1) * H_ + j] = h1v;
            }
        }
        {   // layer-0 cell, t = k+1 (phantom at k = T_-1, harmless)
            float i0 = fsig(aL0[0][0]), i1 = fsig(aL0[0][1]);
            float f0 = fsig(aL0[0][2]), f1 = fsig(aL0[0][3]);
            float g0 = ftanh(aL0[1][0]), g1 = ftanh(aL0[1][1]);
            float o0 = fsig(aL0[1][2]), o1 = fsig(aL0[1][3]);
            c00 = f0 * c00 + i0 * g0;
            c01 = f1 * c01 + i1 * g1;
            h0w[n0 * SHS + j]       = __float2half(o0 * ftanh(c00));
            h0w[(n0 + 1) * SHS + j] = __float2half(o1 * ftanh(c01));
        }
        {   // x pipeline: commit x(k+2) to buf 1-p, fetch x(k+3)
            half* xw = sX + (1 - p) * (BT * SXS);
            *(half2*)(xw + xr * SXS + xi)     = __floats2half2_rn(xpre.x, xpre.y);
            *(half2*)(xw + xr * SXS + xi + 2) = __floats2half2_rn(xpre.z, xpre.w);
            int tn = k + 3; if (tn > T_ - 1) tn = T_ - 1;
            xpre = *(const float4*)(xrow + (size_t)tn * I_);
        }
        __syncthreads();
    }

    // ---- head: emb = relu(h Wp^T+bp); hid = relu(emb W1^T+b1); logits ----
#pragma unroll
    for (int q = 0; q < 4; q++) {
        int idx = tid + q * NTHR;               // 8*128
        int r = idx >> 7, e = idx & 127;
        float a = bproj[e];
        const float* wp = Wproj + e * H_;
        const float* hp = sHF + r * H_;
#pragma unroll 8
        for (int kk = 0; kk < H_; kk++) a += hp[kk] * wp[kk];
        sE[r * E_ + e] = fmaxf(a, 0.f);
    }
    __syncthreads();
#pragma unroll
    for (int q = 0; q < 4; q++) {
        int idx = tid + q * NTHR;
        int r = idx >> 7, e = idx & 127;
        float a = bfc1[e];
        const float* wp = Wfc1 + e * E_;
        const float* hp = sE + r * E_;
#pragma unroll 8
        for (int kk = 0; kk < E_; kk++) a += hp[kk] * wp[kk];
        sF[r * E_ + e] = fmaxf(a, 0.f);
    }
    __syncthreads();
    for (int idx = tid; idx < BT * C_; idx += NTHR) {
        int r = idx / C_, c = idx - r * C_;
        float a = bfc2[c];
        const float* wp = Wfc2 + c * E_;
        const float* hp = sF + r * E_;
#pragma unroll 8
        for (int kk = 0; kk < E_; kk++) a += hp[kk] * wp[kk];
        out[(size_t)(b0r + r) * C_ + c] = a;
    }
}

}  // namespace

extern "C" void kernel_launch(void* const* d_in, const int* in_sizes, int n_in,
                              void* d_out, int out_size) {
    cudaFuncSetAttribute(lstm_fused, cudaFuncAttributeMaxDynamicSharedMemorySize,
                         SMEM_TOTAL);
    lstm_fused<<<NCTA, NTHR, SMEM_TOTAL>>>(
        (const float*)d_in[0],
        (const float*)d_in[1],  (const float*)d_in[2],
        (const float*)d_in[3],  (const float*)d_in[4],
        (const float*)d_in[5],  (const float*)d_in[6],
        (const float*)d_in[7],  (const float*)d_in[8],
        (const float*)d_in[9],  (const float*)d_in[10],
        (const float*)d_in[11], (const float*)d_in[12],
        (const float*)d_in[13], (const float*)d_in[14],
        (float*)d_out);
}

// round 4
// speedup vs baseline: 2.1842x; 1.2176x over previous
#include <cuda_runtime.h>
#include <cuda_fp16.h>
#include <cstdint>

// ---------------------------------------------------------------------------
// Fused persistent LSTM classifier, v3: layer-split warp specialization.
// 128 CTAs x 512 threads. Warps 0-7: layer-0 (W_ih0/W_hh0 frags in regs,
// L0 gates+cell). Warps 8-15: layer-1 (W_ih1/W_hh1 frags, L1 gates+cell,
// x prefetch). Gates stay in the owning warp's accumulators; one barrier
// per time step (count-matched bar.sync 0 from both divergent paths).
// Activations via tanh.approx (1 MUFU each; sigmoid = affine of tanh).
// ---------------------------------------------------------------------------

namespace {

constexpr int T_ = 512, I_ = 128, H_ = 64, E_ = 128, C_ = 100;
constexpr int BT = 8, NCTA = 128, NTHR = 512;

// smem strides (elements)
constexpr int SWI = 136;   // W_ih0 rows (K=128 halves + pad)
constexpr int SWH = 72;    // K=64 weight rows
constexpr int SXS = 136;   // x rows   (LDS conflict-free)
constexpr int SHS = 72;    // h rows   (LDS conflict-free)

// smem offsets (bytes, 16B aligned)
constexpr int OFF_WIH0 = 0;        // 256*136*2 = 69632
constexpr int OFF_WHH0 = 69632;    // 256*72*2  = 36864
constexpr int OFF_WIH1 = 106496;
constexpr int OFF_WHH1 = 143360;
constexpr int OFF_B0   = 180224;   // 256 f32
constexpr int OFF_B1   = 181248;
constexpr int OFF_X    = 182272;   // 2 bufs * 8*136*2 = 4352
constexpr int OFF_H0   = 186624;   // 2 bufs * 8*72*2  = 2304
constexpr int OFF_H1   = 188928;
constexpr int OFF_HF   = 191232;   // 8*64 f32
constexpr int OFF_E    = 193280;   // 8*128 f32
constexpr int OFF_F    = 197376;
constexpr int SMEM_TOTAL = 201472;

#define BARRIER() asm volatile("bar.sync 0;" ::: "memory")

__device__ __forceinline__ float tanh_ap(float x) {
    float y;
    asm("tanh.approx.f32 %0, %1;" : "=f"(y) : "f"(x));
    return y;
}
__device__ __forceinline__ float fsig(float x) {
    return fmaf(0.5f, tanh_ap(0.5f * x), 0.5f);
}

__device__ __forceinline__ void mma4(float c[4], const uint32_t a[4],
                                     uint32_t b0, uint32_t b1) {
    asm volatile(
        "mma.sync.aligned.m16n8k16.row.col.f32.f16.f16.f32 "
        "{%0,%1,%2,%3},{%4,%5,%6,%7},{%8,%9},{%0,%1,%2,%3};\n"
        : "+f"(c[0]), "+f"(c[1]), "+f"(c[2]), "+f"(c[3])
        : "r"(a[0]), "r"(a[1]), "r"(a[2]), "r"(a[3]), "r"(b0), "r"(b1));
}

// One-time: this warp's A-fragments (permuted W rows) -> registers.
template <int KT, int S>
__device__ __forceinline__ void load_w(const half* __restrict__ sW, int wc, int g,
                                       int t, uint32_t f[KT][2][4]) {
#pragma unroll
    for (int kt = 0; kt < KT; kt++)
#pragma unroll
        for (int u = 0; u < 2; u++) {
            const half* p = sW + (wc * 32 + u * 16 + g) * S + kt * 16 + 2 * t;
            f[kt][u][0] = *(const uint32_t*)(p);
            f[kt][u][1] = *(const uint32_t*)(p + 8 * S);
            f[kt][u][2] = *(const uint32_t*)(p + 8);
            f[kt][u][3] = *(const uint32_t*)(p + 8 * S + 8);
        }
}

__device__ __forceinline__ void acc_init(float a[2][4], const float b[2][2]) {
#pragma unroll
    for (int u = 0; u < 2; u++) {
        a[u][0] = b[u][0]; a[u][1] = b[u][0];
        a[u][2] = b[u][1]; a[u][3] = b[u][1];
    }
}

__global__ void __launch_bounds__(NTHR, 1)
lstm_fused(const float* __restrict__ x,
           const float* __restrict__ Wih0, const float* __restrict__ Whh0,
           const float* __restrict__ bih0, const float* __restrict__ bhh0,
           const float* __restrict__ Wih1, const float* __restrict__ Whh1,
           const float* __restrict__ bih1, const float* __restrict__ bhh1,
           const float* __restrict__ Wproj, const float* __restrict__ bproj,
           const float* __restrict__ Wfc1, const float* __restrict__ bfc1,
           const float* __restrict__ Wfc2, const float* __restrict__ bfc2,
           float* __restrict__ out)
{
    extern __shared__ unsigned char smem[];
    half*  sWih0 = (half*)(smem + OFF_WIH0);
    half*  sWhh0 = (half*)(smem + OFF_WHH0);
    half*  sWih1 = (half*)(smem + OFF_WIH1);
    half*  sWhh1 = (half*)(smem + OFF_WHH1);
    float* sB0   = (float*)(smem + OFF_B0);
    float* sB1   = (float*)(smem + OFF_B1);
    half*  sX    = (half*)(smem + OFF_X);
    half*  sH0   = (half*)(smem + OFF_H0);
    half*  sH1   = (half*)(smem + OFF_H1);
    float* sHF   = (float*)(smem + OFF_HF);
    float* sE    = (float*)(smem + OFF_E);
    float* sF    = (float*)(smem + OFF_F);

    const int tid  = threadIdx.x;
    const int lane = tid & 31;
    const int w    = tid >> 5;
    const int wc   = w & 7;           // column-warp index (hidden units wc*8+g)
    const int g    = lane >> 2;
    const int t    = lane & 3;
    const int b0r  = blockIdx.x * BT;

    // ---- stage permuted fp16 weights + fused biases (all 512 threads) ----
    // perm row p = wc*32 + u*16 + v*8 + r  <->  orig m = (2u+v)*64 + wc*8 + r
    for (int i = tid; i < 256 * 128; i += NTHR) {
        int p = i >> 7, k = i & 127;
        int m = (((p >> 4) & 1) * 2 + ((p >> 3) & 1)) * 64 + (p >> 5) * 8 + (p & 7);
        sWih0[p * SWI + k] = __float2half(Wih0[m * 128 + k]);
    }
    for (int i = tid; i < 256 * 64; i += NTHR) {
        int p = i >> 6, k = i & 63;
        int m = (((p >> 4) & 1) * 2 + ((p >> 3) & 1)) * 64 + (p >> 5) * 8 + (p & 7);
        sWhh0[p * SWH + k] = __float2half(Whh0[m * 64 + k]);
        sWih1[p * SWH + k] = __float2half(Wih1[m * 64 + k]);
        sWhh1[p * SWH + k] = __float2half(Whh1[m * 64 + k]);
    }
    for (int i = tid; i < 256; i += NTHR) {
        sB0[i] = bih0[i] + bhh0[i];
        sB1[i] = bih1[i] + bhh1[i];
    }
    for (int i = tid; i < 2 * BT * SHS; i += NTHR) {
        sH1[i] = __float2half(0.f);     // h1(-1) = 0
    }

    // ---- x pipeline owned by L1 warps (8-15): warp=batch row, lane=4 floats ----
    const int xr = wc, xi = lane * 4;
    const float* xrow = x + ((size_t)(b0r + xr) * T_) * I_ + xi;
    float4 xpre = make_float4(0.f, 0.f, 0.f, 0.f);
    if (w >= 8) {
        float4 xv = *(const float4*)(xrow);            // x(0) -> sX buf1
        half* xw = sX + BT * SXS;
        *(half2*)(xw + xr * SXS + xi)     = __floats2half2_rn(xv.x, xv.y);
        *(half2*)(xw + xr * SXS + xi + 2) = __floats2half2_rn(xv.z, xv.w);
        xpre = *(const float4*)(xrow + I_);            // x(1)
    }
    __syncthreads();                                   // (A)

    const int n0 = 2 * t;            // this thread's two batch rows
    const int j  = wc * 8 + g;       // this thread's hidden unit

    if (w < 8) {
        // ================= layer-0 warps =================
        uint32_t fih0[8][2][4], fhh0[4][2][4];
        load_w<8, SWI>(sWih0, wc, g, t, fih0);
        load_w<4, SWH>(sWhh0, wc, g, t, fhh0);
        float bb0[2][2];
#pragma unroll
        for (int u = 0; u < 2; u++)
#pragma unroll
            for (int v = 0; v < 2; v++)
                bb0[u][v] = sB0[(2 * u + v) * 64 + wc * 8 + g];

        float c00 = 0.f, c01 = 0.f;

        {   // prologue: t = 0 cell (h0(-1)=0 -> no recurrent term)
            float a[2][4];
            acc_init(a, bb0);
            const half* X = sX + BT * SXS;
#pragma unroll
            for (int kt = 0; kt < 8; kt++) {
                const half* p = X + g * SXS + kt * 16 + 2 * t;
                uint32_t b0 = *(const uint32_t*)(p);
                uint32_t b1 = *(const uint32_t*)(p + 8);
                mma4(a[0], fih0[kt][0], b0, b1);
                mma4(a[1], fih0[kt][1], b0, b1);
            }
            float i0 = fsig(a[0][0]), i1 = fsig(a[0][1]);
            float g0 = tanh_ap(a[1][0]), g1 = tanh_ap(a[1][1]);
            float o0 = fsig(a[1][2]), o1 = fsig(a[1][3]);
            c00 = i0 * g0; c01 = i1 * g1;
            sH0[n0 * SHS + j]       = __float2half(o0 * tanh_ap(c00));
            sH0[(n0 + 1) * SHS + j] = __float2half(o1 * tanh_ap(c01));
        }
        BARRIER();                                      // S1

        for (int k = 0; k < T_; k++) {
            const int p = k & 1;
            float a[2][4];
            acc_init(a, bb0);
            const half* H0 = sH0 + p * (BT * SHS);
#pragma unroll
            for (int kt = 0; kt < 4; kt++) {
                const half* q = H0 + g * SHS + kt * 16 + 2 * t;
                uint32_t b0 = *(const uint32_t*)(q);
                uint32_t b1 = *(const uint32_t*)(q + 8);
                mma4(a[0], fhh0[kt][0], b0, b1);
                mma4(a[1], fhh0[kt][1], b0, b1);
            }
            const half* X = sX + p * (BT * SXS);
#pragma unroll
            for (int kt = 0; kt < 8; kt++) {
                const half* q = X + g * SXS + kt * 16 + 2 * t;
                uint32_t b0 = *(const uint32_t*)(q);
                uint32_t b1 = *(const uint32_t*)(q + 8);
                mma4(a[0], fih0[kt][0], b0, b1);
                mma4(a[1], fih0[kt][1], b0, b1);
            }
            // L0 cell for t = k+1 (phantom at k = T_-1, harmless)
            float i0 = fsig(a[0][0]), i1 = fsig(a[0][1]);
            float f0 = fsig(a[0][2]), f1 = fsig(a[0][3]);
            float g0 = tanh_ap(a[1][0]), g1 = tanh_ap(a[1][1]);
            float o0 = fsig(a[1][2]), o1 = fsig(a[1][3]);
            c00 = f0 * c00 + i0 * g0;
            c01 = f1 * c01 + i1 * g1;
            half* h0w = sH0 + (1 - p) * (BT * SHS);
            h0w[n0 * SHS + j]       = __float2half(o0 * tanh_ap(c00));
            h0w[(n0 + 1) * SHS + j] = __float2half(o1 * tanh_ap(c01));
            BARRIER();
        }
    } else {
        // ================= layer-1 warps =================
        uint32_t fih1[4][2][4], fhh1[4][2][4];
        load_w<4, SWH>(sWih1, wc, g, t, fih1);
        load_w<4, SWH>(sWhh1, wc, g, t, fhh1);
        float bb1[2][2];
#pragma unroll
        for (int u = 0; u < 2; u++)
#pragma unroll
            for (int v = 0; v < 2; v++)
                bb1[u][v] = sB1[(2 * u + v) * 64 + wc * 8 + g];

        float c10 = 0.f, c11 = 0.f;

        {   // commit x(1) -> sX buf0, fetch x(2)
            half* xw = sX;
            *(half2*)(xw + xr * SXS + xi)     = __floats2half2_rn(xpre.x, xpre.y);
            *(half2*)(xw + xr * SXS + xi + 2) = __floats2half2_rn(xpre.z, xpre.w);
            xpre = *(const float4*)(xrow + 2 * (size_t)I_);
        }
        BARRIER();                                      // S1

        for (int k = 0; k < T_; k++) {
            const int p = k & 1;
            float a[2][4];
            acc_init(a, bb1);
            const half* H0 = sH0 + p * (BT * SHS);
            const half* H1 = sH1 + p * (BT * SHS);
#pragma unroll
            for (int kt = 0; kt < 4; kt++) {
                const half* q0 = H0 + g * SHS + kt * 16 + 2 * t;
                uint32_t b0 = *(const uint32_t*)(q0);
                uint32_t b1 = *(const uint32_t*)(q0 + 8);
                mma4(a[0], fih1[kt][0], b0, b1);
                mma4(a[1], fih1[kt][1], b0, b1);
                const half* q1 = H1 + g * SHS + kt * 16 + 2 * t;
                uint32_t d0 = *(const uint32_t*)(q1);
                uint32_t d1 = *(const uint32_t*)(q1 + 8);
                mma4(a[0], fhh1[kt][0], d0, d1);
                mma4(a[1], fhh1[kt][1], d0, d1);
            }
            {   // x pipeline: commit x(k+2) -> buf 1-p, fetch x(k+3)
                half* xw = sX + (1 - p) * (BT * SXS);
                *(half2*)(xw + xr * SXS + xi)     = __floats2half2_rn(xpre.x, xpre.y);
                *(half2*)(xw + xr * SXS + xi + 2) = __floats2half2_rn(xpre.z, xpre.w);
                int tn = k + 3; if (tn > T_ - 1) tn = T_ - 1;
                xpre = *(const float4*)(xrow + (size_t)tn * I_);
            }
            // L1 cell for t = k
            float i0 = fsig(a[0][0]), i1 = fsig(a[0][1]);
            float f0 = fsig(a[0][2]), f1 = fsig(a[0][3]);
            float g0 = tanh_ap(a[1][0]), g1 = tanh_ap(a[1][1]);
            float o0 = fsig(a[1][2]), o1 = fsig(a[1][3]);
            c10 = f0 * c10 + i0 * g0;
            c11 = f1 * c11 + i1 * g1;
            float h0v = o0 * tanh_ap(c10), h1v = o1 * tanh_ap(c11);
            half* h1w = sH1 + (1 - p) * (BT * SHS);
            h1w[n0 * SHS + j]       = __float2half(h0v);
            h1w[(n0 + 1) * SHS + j] = __float2half(h1v);
            if (k == T_ - 1) {
                sHF[n0 * H_ + j]       = h0v;
                sHF[(n0 + 1) * H_ + j] = h1v;
            }
            BARRIER();
        }
    }

    // ---- head (all 512 threads): proj -> relu -> fc1 -> relu -> fc2 ----
#pragma unroll
    for (int q = 0; q < 2; q++) {
        int idx = tid + q * NTHR;                 // 1024 outputs
        int r = idx >> 7, e = idx & 127;
        float a = bproj[e];
        const float* wp = Wproj + e * H_;
        const float* hp = sHF + r * H_;
#pragma unroll 8
        for (int kk = 0; kk < H_; kk++) a += hp[kk] * wp[kk];
        sE[r * E_ + e] = fmaxf(a, 0.f);
    }
    __syncthreads();
#pragma unroll
    for (int q = 0; q < 2; q++) {
        int idx = tid + q * NTHR;
        int r = idx >> 7, e = idx & 127;
        float a = bfc1[e];
        const float* wp = Wfc1 + e * E_;
        const float* hp = sE + r * E_;
#pragma unroll 8
        for (int kk = 0; kk < E_; kk++) a += hp[kk] * wp[kk];
        sF[r * E_ + e] = fmaxf(a, 0.f);
    }
    __syncthreads();
    for (int idx = tid; idx < BT * C_; idx += NTHR) {
        int r = idx / C_, c = idx - r * C_;
        float a = bfc2[c];
        const float* wp = Wfc2 + c * E_;
        const float* hp = sF + r * E_;
#pragma unroll 8
        for (int kk = 0; kk < E_; kk++) a += hp[kk] * wp[kk];
        out[(size_t)(b0r + r) * C_ + c] = a;
    }
}

}  // namespace

extern "C" void kernel_launch(void* const* d_in, const int* in_sizes, int n_in,
                              void* d_out, int out_size) {
    cudaFuncSetAttribute(lstm_fused, cudaFuncAttributeMaxDynamicSharedMemorySize,
                         SMEM_TOTAL);
    lstm_fused<<<NCTA, NTHR, SMEM_TOTAL>>>(
        (const float*)d_in[0],
        (const float*)d_in[1],  (const float*)d_in[2],
        (const float*)d_in[3],  (const float*)d_in[4],
        (const float*)d_in[5],  (const float*)d_in[6],
        (const float*)d_in[7],  (const float*)d_in[8],
        (const float*)d_in[9],  (const float*)d_in[10],
        (const float*)d_in[11], (const float*)d_in[12],
        (const float*)d_in[13], (const float*)d_in[14],
        (float*)d_out);
}